// round 16
// baseline (speedup 1.0000x reference)
#include <cuda_runtime.h>
#include <cuda_fp16.h>
#include <cstdint>

// Causal MHA, B=2, L=2048, H=16, E=64, fp32; reference scales scores by sqrt(E)=8.
// R15: R13 body (prepack + cp.async attn, ldmatrix frags, fp16 m16n8k16,
// QK 3-term / PV 1-term, deferred l-reduction, log2 softmax, 3 CTAs/SM) with:
//   - distance-1 / SINGLE-barrier pipeline (stage(t+1) at top of iter t;
//     bottom barrier proven redundant)
//   - diagonal-tile MMA skipping (warp-uniform: jp>w QK tiles fully masked,
//     kk>w P-chunks exactly zero)

#define NT 128
#define BM 64
#define BN 64
#define ED 64
#define ST32 36                  // uint32 row stride = 144 B (9 x 16B), ldsm-clean

static constexpr int B_ = 2, L_ = 2048, H_ = 16;
static constexpr int RS = H_ * ED;                    // 1024 floats per seq row
static constexpr int ARR  = BN * ST32;                // 2304 uint32 per smem array
static constexpr int ARRB = ARR * 4;                  // 9216 B
static constexpr int BUFB = 3 * ARRB;                 // 27648 B per buffer
static constexpr int SMEM_BYTES = 2 * BUFB;           // 55296 B

// Pre-packed K/V: [b][h][kt(32)][row(64)][pair(32 uint32)] -> 2048 uint32/tile
static constexpr int GPK = 2 * 16 * 32 * 2048;        // 8MB each
__device__ uint32_t gKh[GPK];
__device__ uint32_t gKl[GPK];
__device__ uint32_t gVh[GPK];

__device__ __forceinline__ uint32_t pack_f16x2(float lo, float hi) {
    uint32_t d;   // PTX: first source -> upper half
    asm("cvt.rn.f16x2.f32 %0, %1, %2;" : "=r"(d) : "f"(hi), "f"(lo));
    return d;
}
__device__ __forceinline__ float2 unpack_f16x2(uint32_t u) {
    __half2 h = *reinterpret_cast<__half2*>(&u);
    return __half22float2(h);
}

__device__ __forceinline__ float ex2(float x) {
    float y;
    asm("ex2.approx.f32 %0, %1;" : "=f"(y) : "f"(x));
    return y;
}

__device__ __forceinline__ void ldsm4(uint32_t& d0, uint32_t& d1,
                                      uint32_t& d2, uint32_t& d3, uint32_t a) {
    asm volatile("ldmatrix.sync.aligned.m8n8.x4.shared.b16 {%0,%1,%2,%3}, [%4];"
                 : "=r"(d0), "=r"(d1), "=r"(d2), "=r"(d3) : "r"(a));
}
__device__ __forceinline__ void ldsm4t(uint32_t& d0, uint32_t& d1,
                                       uint32_t& d2, uint32_t& d3, uint32_t a) {
    asm volatile("ldmatrix.sync.aligned.m8n8.x4.trans.shared.b16 {%0,%1,%2,%3}, [%4];"
                 : "=r"(d0), "=r"(d1), "=r"(d2), "=r"(d3) : "r"(a));
}

__device__ __forceinline__ void mma_f16(float c[4],
                                        uint32_t a0, uint32_t a1, uint32_t a2, uint32_t a3,
                                        uint32_t b0, uint32_t b1) {
    asm volatile(
        "mma.sync.aligned.m16n8k16.row.col.f32.f16.f16.f32 "
        "{%0,%1,%2,%3}, {%4,%5,%6,%7}, {%8,%9}, {%0,%1,%2,%3};"
        : "+f"(c[0]), "+f"(c[1]), "+f"(c[2]), "+f"(c[3])
        : "r"(a0), "r"(a1), "r"(a2), "r"(a3), "r"(b0), "r"(b1));
}

__device__ __forceinline__ void cp16(uint32_t dst, const void* src) {
    asm volatile("cp.async.cg.shared.global [%0], [%1], 16;\n"
                 :: "r"(dst), "l"(src));
}

// ---------- pre-pack kernel: K -> fp16 hi/lo, V -> fp16 hi, tile-blocked ----------
__global__ void prepack_kernel(const float* __restrict__ K,
                               const float* __restrict__ V)
{
    int id = blockIdx.x * blockDim.x + threadIdx.x;    // one float4 of K and V
    if (id >= B_ * L_ * H_ * (ED / 4)) return;
    int e4 = id & 15;
    size_t src = (size_t)(id >> 4) * 64 + e4 * 4;      // ((b*L+n)*H+h)*64 + e
    int n  = (id >> 8) & (L_ - 1);
    int h  = (id >> 4) & 15;
    int b  = id >> 19;
    int nt  = n >> 6;
    int row = n & 63;
    uint32_t dst = ((((b * 16 + h) * 32 + nt) * 64 + row) << 5) + e4 * 2;

    float4 kf = *reinterpret_cast<const float4*>(K + src);
    uint32_t kh01 = pack_f16x2(kf.x, kf.y);
    uint32_t kh23 = pack_f16x2(kf.z, kf.w);
    float2 kd01 = unpack_f16x2(kh01);
    float2 kd23 = unpack_f16x2(kh23);
    uint32_t kl01 = pack_f16x2(kf.x - kd01.x, kf.y - kd01.y);
    uint32_t kl23 = pack_f16x2(kf.z - kd23.x, kf.w - kd23.y);
    *reinterpret_cast<uint2*>(&gKh[dst]) = make_uint2(kh01, kh23);
    *reinterpret_cast<uint2*>(&gKl[dst]) = make_uint2(kl01, kl23);

    float4 vf = *reinterpret_cast<const float4*>(V + src);
    uint32_t vh01 = pack_f16x2(vf.x, vf.y);
    uint32_t vh23 = pack_f16x2(vf.z, vf.w);
    *reinterpret_cast<uint2*>(&gVh[dst]) = make_uint2(vh01, vh23);
}

// ---------- attention kernel ----------
__global__ __launch_bounds__(NT, 3) void attn_kernel(
    const float* __restrict__ Q, float* __restrict__ O)
{
    extern __shared__ uint32_t smu[];
    const uint32_t smb = (uint32_t)__cvta_generic_to_shared(smu);

    const int tid  = threadIdx.x;
    const int lane = tid & 31;
    const int w    = tid >> 5;            // 0..3
    const int r    = lane >> 2;           // 0..7
    const int c    = lane & 3;            // 0..3
    const int rr8  = lane & 7;
    const int msel = lane >> 3;
    const int qt = (int)gridDim.x - 1 - (int)blockIdx.x;   // heavy tiles first
    const int h  = blockIdx.y, b = blockIdx.z;
    const int q0 = qt * BM;
    const int m_lo = q0 + w * 16 + r;
    const size_t base = ((size_t)b * L_ * H_ + h) * ED;
    const float* Qp = Q + base;
    float*       Op = O + base;

    const uint32_t laneK = (uint32_t)(((msel >> 1) * 8 + rr8) * 144 + (msel & 1) * 16);
    const uint32_t laneV = (uint32_t)(((msel & 1) * 8 + rr8) * 144 + (msel >> 1) * 16);
    const uint32_t tbase = (uint32_t)((b * 16 + h) * 32) << 11;   // *2048

    // ---- Q A-fragments: scale 8*log2(e), fp16 hi/lo split, resident ----
    const float QS = 8.f * 1.4426950408889634f;
    uint32_t qh[4][4], ql[4][4];
    #pragma unroll
    for (int kk = 0; kk < 4; ++kk) {
        const float* p = Qp + (size_t)m_lo * RS + kk * 16 + 2 * c;
        float2 x0 = *reinterpret_cast<const float2*>(p);
        float2 x1 = *reinterpret_cast<const float2*>(p + 8 * RS);
        float2 x2 = *reinterpret_cast<const float2*>(p + 8);
        float2 x3 = *reinterpret_cast<const float2*>(p + 8 * RS + 8);
        float f[4][2] = { {QS*x0.x, QS*x0.y}, {QS*x1.x, QS*x1.y},
                          {QS*x2.x, QS*x2.y}, {QS*x3.x, QS*x3.y} };
        #pragma unroll
        for (int i = 0; i < 4; ++i) {
            uint32_t hh = pack_f16x2(f[i][0], f[i][1]);
            float2 d = unpack_f16x2(hh);
            qh[kk][i] = hh;
            ql[kk][i] = pack_f16x2(f[i][0] - d.x, f[i][1] - d.y);
        }
    }

    float acc[8][4];
    #pragma unroll
    for (int j = 0; j < 8; ++j)
        #pragma unroll
        for (int i = 0; i < 4; ++i) acc[j][i] = 0.f;

    float mr0 = -1e30f, mr1 = -1e30f;
    float l0 = 0.f, l1 = 0.f;

    const int nTiles = qt + 1;

    auto stageTile = [&](int kt, int bufsel) {
        if (kt < nTiles) {
            const uint32_t tb = tbase + ((uint32_t)kt << 11);
            const uint32_t sb = smb + bufsel * BUFB;
            #pragma unroll
            for (int t = 0; t < 4; ++t) {
                int ch = tid + t * NT;          // 0..511
                int row = ch >> 3;
                int c16 = ch & 7;
                uint32_t gi = tb + (row << 5) + c16 * 4;
                uint32_t sd = sb + row * 144 + c16 * 16;
                cp16(sd,          &gKh[gi]);
                cp16(sd + ARRB,   &gKl[gi]);
                cp16(sd + 2*ARRB, &gVh[gi]);
            }
        }
        asm volatile("cp.async.commit_group;\n" ::: "memory");
    };

    stageTile(0, 0);

    for (int kt = 0; kt < nTiles; ++kt) {
        const int k0 = kt * BN;
        const bool diag = (kt == qt);

        // wait for this tile's copies; single barrier per tile.
        asm volatile("cp.async.wait_group 0;\n" ::: "memory");
        __syncthreads();
        // buf[(kt+1)&1] was last read in iteration kt-1 (all warps past the
        // barrier above are done with it) -> safe to stage now, no 2nd barrier.
        stageTile(kt + 1, (kt + 1) & 1);

        const uint32_t sb  = smb + (kt & 1) * BUFB;
        const uint32_t KhB = sb, KlB = sb + ARRB, VhB = sb + 2 * ARRB;

        // ---- S = Q K^T (log2 domain), 3-term fp16, ldmatrix B-frags ----
        float s[8][4];
        #pragma unroll
        for (int j = 0; j < 8; ++j)
            #pragma unroll
            for (int i = 0; i < 4; ++i) s[j][i] = 0.f;

        #pragma unroll
        for (int kk = 0; kk < 4; ++kk) {
            #pragma unroll
            for (int jp = 0; jp < 4; ++jp) {
                if (diag && jp > w) continue;   // tiles fully above diagonal
                const uint32_t off = laneK + jp * 2304 + kk * 32;
                uint32_t kh0, kh1, kh2, kh3, kl0, kl1, kl2, kl3;
                ldsm4(kh0, kh1, kh2, kh3, KhB + off);
                ldsm4(kl0, kl1, kl2, kl3, KlB + off);
                mma_f16(s[2*jp],   qh[kk][0], qh[kk][1], qh[kk][2], qh[kk][3], kh0, kh1);
                mma_f16(s[2*jp],   ql[kk][0], ql[kk][1], ql[kk][2], ql[kk][3], kh0, kh1);
                mma_f16(s[2*jp],   qh[kk][0], qh[kk][1], qh[kk][2], qh[kk][3], kl0, kl1);
                mma_f16(s[2*jp+1], qh[kk][0], qh[kk][1], qh[kk][2], qh[kk][3], kh2, kh3);
                mma_f16(s[2*jp+1], ql[kk][0], ql[kk][1], ql[kk][2], ql[kk][3], kh2, kh3);
                mma_f16(s[2*jp+1], qh[kk][0], qh[kk][1], qh[kk][2], qh[kk][3], kl2, kl3);
            }
        }

        // ---- causal mask (diagonal tile only; also covers skipped tiles) ----
        if (diag) {
            #pragma unroll
            for (int j = 0; j < 8; ++j) {
                int n = k0 + j * 8 + 2 * c;
                if (n     > m_lo)     s[j][0] = -1e30f;
                if (n + 1 > m_lo)     s[j][1] = -1e30f;
                if (n     > m_lo + 8) s[j][2] = -1e30f;
                if (n + 1 > m_lo + 8) s[j][3] = -1e30f;
            }
        }

        // ---- online softmax: only MAX reduced; l stays per-lane ----
        float mx0 = -1e30f, mx1 = -1e30f;
        #pragma unroll
        for (int j = 0; j < 8; ++j) {
            mx0 = fmaxf(mx0, fmaxf(s[j][0], s[j][1]));
            mx1 = fmaxf(mx1, fmaxf(s[j][2], s[j][3]));
        }
        mx0 = fmaxf(mx0, __shfl_xor_sync(0xffffffffu, mx0, 1));
        mx0 = fmaxf(mx0, __shfl_xor_sync(0xffffffffu, mx0, 2));
        mx1 = fmaxf(mx1, __shfl_xor_sync(0xffffffffu, mx1, 1));
        mx1 = fmaxf(mx1, __shfl_xor_sync(0xffffffffu, mx1, 2));

        float mn0 = fmaxf(mr0, mx0), mn1 = fmaxf(mr1, mx1);
        float al0 = ex2(mr0 - mn0), al1 = ex2(mr1 - mn1);
        float sum0 = 0.f, sum1 = 0.f;
        #pragma unroll
        for (int j = 0; j < 8; ++j) {
            s[j][0] = ex2(s[j][0] - mn0);
            s[j][1] = ex2(s[j][1] - mn0);
            s[j][2] = ex2(s[j][2] - mn1);
            s[j][3] = ex2(s[j][3] - mn1);
            sum0 += s[j][0] + s[j][1];
            sum1 += s[j][2] + s[j][3];
        }
        l0 = l0 * al0 + sum0;
        l1 = l1 * al1 + sum1;
        mr0 = mn0; mr1 = mn1;

        #pragma unroll
        for (int j = 0; j < 8; ++j) {
            acc[j][0] *= al0; acc[j][1] *= al0;
            acc[j][2] *= al1; acc[j][3] *= al1;
        }

        // ---- O += P V : 1-term fp16 (ph*vh), ldmatrix.trans B ----
        #pragma unroll
        for (int kk = 0; kk < 4; ++kk) {
            if (diag && kk > w) continue;       // P chunk exactly zero
            uint32_t ph0 = pack_f16x2(s[2*kk][0],   s[2*kk][1]);
            uint32_t ph1 = pack_f16x2(s[2*kk][2],   s[2*kk][3]);
            uint32_t ph2 = pack_f16x2(s[2*kk+1][0], s[2*kk+1][1]);
            uint32_t ph3 = pack_f16x2(s[2*kk+1][2], s[2*kk+1][3]);
            #pragma unroll
            for (int jp = 0; jp < 4; ++jp) {
                const uint32_t off = laneV + kk * 2304 + jp * 32;
                uint32_t vh0, vh1, vh2, vh3;
                ldsm4t(vh0, vh1, vh2, vh3, VhB + off);
                mma_f16(acc[2*jp],   ph0, ph1, ph2, ph3, vh0, vh1);
                mma_f16(acc[2*jp+1], ph0, ph1, ph2, ph3, vh2, vh3);
            }
        }
    }

    // ---- epilogue: reduce l across the quad, normalize, store ----
    l0 += __shfl_xor_sync(0xffffffffu, l0, 1);
    l0 += __shfl_xor_sync(0xffffffffu, l0, 2);
    l1 += __shfl_xor_sync(0xffffffffu, l1, 1);
    l1 += __shfl_xor_sync(0xffffffffu, l1, 2);
    const float inv0 = 1.f / l0, inv1 = 1.f / l1;
    #pragma unroll
    for (int jj = 0; jj < 8; ++jj) {
        float2 o0 = { acc[jj][0] * inv0, acc[jj][1] * inv0 };
        float2 o1 = { acc[jj][2] * inv1, acc[jj][3] * inv1 };
        *reinterpret_cast<float2*>(Op + (size_t)m_lo * RS + jj * 8 + 2 * c) = o0;
        *reinterpret_cast<float2*>(Op + (size_t)(m_lo + 8) * RS + jj * 8 + 2 * c) = o1;
    }
}

extern "C" void kernel_launch(void* const* d_in, const int* in_sizes, int n_in,
                              void* d_out, int out_size)
{
    const float* Q = (const float*)d_in[0];
    const float* K = (const float*)d_in[1];
    const float* V = (const float*)d_in[2];
    // d_in[3] = attn_mask (causal triu(k=1)) — applied analytically in-kernel.
    float* O = (float*)d_out;

    // 1) pre-pack K (hi/lo) and V (hi), tile-blocked
    int total = B_ * L_ * H_ * (ED / 4);
    prepack_kernel<<<(total + 255) / 256, 256>>>(K, V);

    // 2) attention
    cudaFuncSetAttribute(attn_kernel, cudaFuncAttributeMaxDynamicSharedMemorySize,
                         SMEM_BYTES);
    dim3 grid(L_ / BM, H_, B_);   // 32 x 16 x 2
    attn_kernel<<<grid, NT, SMEM_BYTES>>>(Q, O);
}

// round 17
// speedup vs baseline: 1.1058x; 1.1058x over previous
#include <cuda_runtime.h>
#include <cuda_fp16.h>
#include <cstdint>

// Causal MHA, B=2, L=2048, H=16, E=64, fp32; reference scales scores by sqrt(E)=8.
// R16: exact R13 body (prepack + cp.async distance-2 two-barrier pipeline,
// ldmatrix frags, fp16 m16n8k16, QK 3-term / PV 1-term, deferred l-reduction,
// log2 softmax, 3 CTAs/SM) with the DIAGONAL TILE PEELED out of the main loop:
//   - main loop (kt < qt): branch-free hot path, no mask test
//   - peeled diag tile: runtime-bounded jp<=w / kk<=w loops (skips are exact)

#define NT 128
#define BM 64
#define BN 64
#define ED 64
#define ST32 36                  // uint32 row stride = 144 B (9 x 16B), ldsm-clean

static constexpr int B_ = 2, L_ = 2048, H_ = 16;
static constexpr int RS = H_ * ED;                    // 1024 floats per seq row
static constexpr int ARR  = BN * ST32;                // 2304 uint32 per smem array
static constexpr int ARRB = ARR * 4;                  // 9216 B
static constexpr int BUFB = 3 * ARRB;                 // 27648 B per buffer
static constexpr int SMEM_BYTES = 2 * BUFB;           // 55296 B

// Pre-packed K/V: [b][h][kt(32)][row(64)][pair(32 uint32)] -> 2048 uint32/tile
static constexpr int GPK = 2 * 16 * 32 * 2048;        // 8MB each
__device__ uint32_t gKh[GPK];
__device__ uint32_t gKl[GPK];
__device__ uint32_t gVh[GPK];

__device__ __forceinline__ uint32_t pack_f16x2(float lo, float hi) {
    uint32_t d;   // PTX: first source -> upper half
    asm("cvt.rn.f16x2.f32 %0, %1, %2;" : "=r"(d) : "f"(hi), "f"(lo));
    return d;
}
__device__ __forceinline__ float2 unpack_f16x2(uint32_t u) {
    __half2 h = *reinterpret_cast<__half2*>(&u);
    return __half22float2(h);
}

__device__ __forceinline__ float ex2(float x) {
    float y;
    asm("ex2.approx.f32 %0, %1;" : "=f"(y) : "f"(x));
    return y;
}

__device__ __forceinline__ void ldsm4(uint32_t& d0, uint32_t& d1,
                                      uint32_t& d2, uint32_t& d3, uint32_t a) {
    asm volatile("ldmatrix.sync.aligned.m8n8.x4.shared.b16 {%0,%1,%2,%3}, [%4];"
                 : "=r"(d0), "=r"(d1), "=r"(d2), "=r"(d3) : "r"(a));
}
__device__ __forceinline__ void ldsm4t(uint32_t& d0, uint32_t& d1,
                                       uint32_t& d2, uint32_t& d3, uint32_t a) {
    asm volatile("ldmatrix.sync.aligned.m8n8.x4.trans.shared.b16 {%0,%1,%2,%3}, [%4];"
                 : "=r"(d0), "=r"(d1), "=r"(d2), "=r"(d3) : "r"(a));
}

__device__ __forceinline__ void mma_f16(float c[4],
                                        uint32_t a0, uint32_t a1, uint32_t a2, uint32_t a3,
                                        uint32_t b0, uint32_t b1) {
    asm volatile(
        "mma.sync.aligned.m16n8k16.row.col.f32.f16.f16.f32 "
        "{%0,%1,%2,%3}, {%4,%5,%6,%7}, {%8,%9}, {%0,%1,%2,%3};"
        : "+f"(c[0]), "+f"(c[1]), "+f"(c[2]), "+f"(c[3])
        : "r"(a0), "r"(a1), "r"(a2), "r"(a3), "r"(b0), "r"(b1));
}

__device__ __forceinline__ void cp16(uint32_t dst, const void* src) {
    asm volatile("cp.async.cg.shared.global [%0], [%1], 16;\n"
                 :: "r"(dst), "l"(src));
}

// ---------- pre-pack kernel: K -> fp16 hi/lo, V -> fp16 hi, tile-blocked ----------
__global__ void prepack_kernel(const float* __restrict__ K,
                               const float* __restrict__ V)
{
    int id = blockIdx.x * blockDim.x + threadIdx.x;    // one float4 of K and V
    if (id >= B_ * L_ * H_ * (ED / 4)) return;
    int e4 = id & 15;
    size_t src = (size_t)(id >> 4) * 64 + e4 * 4;      // ((b*L+n)*H+h)*64 + e
    int n  = (id >> 8) & (L_ - 1);
    int h  = (id >> 4) & 15;
    int b  = id >> 19;
    int nt  = n >> 6;
    int row = n & 63;
    uint32_t dst = ((((b * 16 + h) * 32 + nt) * 64 + row) << 5) + e4 * 2;

    float4 kf = *reinterpret_cast<const float4*>(K + src);
    uint32_t kh01 = pack_f16x2(kf.x, kf.y);
    uint32_t kh23 = pack_f16x2(kf.z, kf.w);
    float2 kd01 = unpack_f16x2(kh01);
    float2 kd23 = unpack_f16x2(kh23);
    uint32_t kl01 = pack_f16x2(kf.x - kd01.x, kf.y - kd01.y);
    uint32_t kl23 = pack_f16x2(kf.z - kd23.x, kf.w - kd23.y);
    *reinterpret_cast<uint2*>(&gKh[dst]) = make_uint2(kh01, kh23);
    *reinterpret_cast<uint2*>(&gKl[dst]) = make_uint2(kl01, kl23);

    float4 vf = *reinterpret_cast<const float4*>(V + src);
    uint32_t vh01 = pack_f16x2(vf.x, vf.y);
    uint32_t vh23 = pack_f16x2(vf.z, vf.w);
    *reinterpret_cast<uint2*>(&gVh[dst]) = make_uint2(vh01, vh23);
}

// ---------- attention kernel ----------
__global__ __launch_bounds__(NT, 3) void attn_kernel(
    const float* __restrict__ Q, float* __restrict__ O)
{
    extern __shared__ uint32_t smu[];
    const uint32_t smb = (uint32_t)__cvta_generic_to_shared(smu);

    const int tid  = threadIdx.x;
    const int lane = tid & 31;
    const int w    = tid >> 5;            // 0..3
    const int r    = lane >> 2;           // 0..7
    const int c    = lane & 3;            // 0..3
    const int rr8  = lane & 7;
    const int msel = lane >> 3;
    const int qt = (int)gridDim.x - 1 - (int)blockIdx.x;   // heavy tiles first
    const int h  = blockIdx.y, b = blockIdx.z;
    const int q0 = qt * BM;
    const int m_lo = q0 + w * 16 + r;
    const size_t base = ((size_t)b * L_ * H_ + h) * ED;
    const float* Qp = Q + base;
    float*       Op = O + base;

    const uint32_t laneK = (uint32_t)(((msel >> 1) * 8 + rr8) * 144 + (msel & 1) * 16);
    const uint32_t laneV = (uint32_t)(((msel & 1) * 8 + rr8) * 144 + (msel >> 1) * 16);
    const uint32_t tbase = (uint32_t)((b * 16 + h) * 32) << 11;   // *2048

    // ---- Q A-fragments: scale 8*log2(e), fp16 hi/lo split, resident ----
    const float QS = 8.f * 1.4426950408889634f;
    uint32_t qh[4][4], ql[4][4];
    #pragma unroll
    for (int kk = 0; kk < 4; ++kk) {
        const float* p = Qp + (size_t)m_lo * RS + kk * 16 + 2 * c;
        float2 x0 = *reinterpret_cast<const float2*>(p);
        float2 x1 = *reinterpret_cast<const float2*>(p + 8 * RS);
        float2 x2 = *reinterpret_cast<const float2*>(p + 8);
        float2 x3 = *reinterpret_cast<const float2*>(p + 8 * RS + 8);
        float f[4][2] = { {QS*x0.x, QS*x0.y}, {QS*x1.x, QS*x1.y},
                          {QS*x2.x, QS*x2.y}, {QS*x3.x, QS*x3.y} };
        #pragma unroll
        for (int i = 0; i < 4; ++i) {
            uint32_t hh = pack_f16x2(f[i][0], f[i][1]);
            float2 d = unpack_f16x2(hh);
            qh[kk][i] = hh;
            ql[kk][i] = pack_f16x2(f[i][0] - d.x, f[i][1] - d.y);
        }
    }

    float acc[8][4];
    #pragma unroll
    for (int j = 0; j < 8; ++j)
        #pragma unroll
        for (int i = 0; i < 4; ++i) acc[j][i] = 0.f;

    float mr0 = -1e30f, mr1 = -1e30f;
    float l0 = 0.f, l1 = 0.f;

    const int nTiles = qt + 1;

    auto stageTile = [&](int kt, int bufsel) {
        if (kt < nTiles) {
            const uint32_t tb = tbase + ((uint32_t)kt << 11);
            const uint32_t sb = smb + bufsel * BUFB;
            #pragma unroll
            for (int t = 0; t < 4; ++t) {
                int ch = tid + t * NT;          // 0..511
                int row = ch >> 3;
                int c16 = ch & 7;
                uint32_t gi = tb + (row << 5) + c16 * 4;
                uint32_t sd = sb + row * 144 + c16 * 16;
                cp16(sd,          &gKh[gi]);
                cp16(sd + ARRB,   &gKl[gi]);
                cp16(sd + 2*ARRB, &gVh[gi]);
            }
        }
        asm volatile("cp.async.commit_group;\n" ::: "memory");
    };

    // softmax + rescale helper (identical math to R13)
    auto softmax_update = [&](float s[8][4]) {
        float mx0 = -1e30f, mx1 = -1e30f;
        #pragma unroll
        for (int j = 0; j < 8; ++j) {
            mx0 = fmaxf(mx0, fmaxf(s[j][0], s[j][1]));
            mx1 = fmaxf(mx1, fmaxf(s[j][2], s[j][3]));
        }
        mx0 = fmaxf(mx0, __shfl_xor_sync(0xffffffffu, mx0, 1));
        mx0 = fmaxf(mx0, __shfl_xor_sync(0xffffffffu, mx0, 2));
        mx1 = fmaxf(mx1, __shfl_xor_sync(0xffffffffu, mx1, 1));
        mx1 = fmaxf(mx1, __shfl_xor_sync(0xffffffffu, mx1, 2));

        float mn0 = fmaxf(mr0, mx0), mn1 = fmaxf(mr1, mx1);
        float al0 = ex2(mr0 - mn0), al1 = ex2(mr1 - mn1);
        float sum0 = 0.f, sum1 = 0.f;
        #pragma unroll
        for (int j = 0; j < 8; ++j) {
            s[j][0] = ex2(s[j][0] - mn0);
            s[j][1] = ex2(s[j][1] - mn0);
            s[j][2] = ex2(s[j][2] - mn1);
            s[j][3] = ex2(s[j][3] - mn1);
            sum0 += s[j][0] + s[j][1];
            sum1 += s[j][2] + s[j][3];
        }
        l0 = l0 * al0 + sum0;
        l1 = l1 * al1 + sum1;
        mr0 = mn0; mr1 = mn1;
        #pragma unroll
        for (int j = 0; j < 8; ++j) {
            acc[j][0] *= al0; acc[j][1] *= al0;
            acc[j][2] *= al1; acc[j][3] *= al1;
        }
    };

    stageTile(0, 0);
    stageTile(1, 1);

    // ================= main loop: kt = 0 .. qt-1 (branch-free hot path) =====
    for (int kt = 0; kt < qt; ++kt) {
        asm volatile("cp.async.wait_group 1;\n" ::: "memory");
        __syncthreads();

        const uint32_t sb  = smb + (kt & 1) * BUFB;
        const uint32_t KhB = sb, KlB = sb + ARRB, VhB = sb + 2 * ARRB;

        float s[8][4];
        #pragma unroll
        for (int j = 0; j < 8; ++j)
            #pragma unroll
            for (int i = 0; i < 4; ++i) s[j][i] = 0.f;

        #pragma unroll
        for (int kk = 0; kk < 4; ++kk) {
            #pragma unroll
            for (int jp = 0; jp < 4; ++jp) {
                const uint32_t off = laneK + jp * 2304 + kk * 32;
                uint32_t kh0, kh1, kh2, kh3, kl0, kl1, kl2, kl3;
                ldsm4(kh0, kh1, kh2, kh3, KhB + off);
                ldsm4(kl0, kl1, kl2, kl3, KlB + off);
                mma_f16(s[2*jp],   qh[kk][0], qh[kk][1], qh[kk][2], qh[kk][3], kh0, kh1);
                mma_f16(s[2*jp],   ql[kk][0], ql[kk][1], ql[kk][2], ql[kk][3], kh0, kh1);
                mma_f16(s[2*jp],   qh[kk][0], qh[kk][1], qh[kk][2], qh[kk][3], kl0, kl1);
                mma_f16(s[2*jp+1], qh[kk][0], qh[kk][1], qh[kk][2], qh[kk][3], kh2, kh3);
                mma_f16(s[2*jp+1], ql[kk][0], ql[kk][1], ql[kk][2], ql[kk][3], kh2, kh3);
                mma_f16(s[2*jp+1], qh[kk][0], qh[kk][1], qh[kk][2], qh[kk][3], kl2, kl3);
            }
        }

        softmax_update(s);

        #pragma unroll
        for (int kk = 0; kk < 4; ++kk) {
            uint32_t ph0 = pack_f16x2(s[2*kk][0],   s[2*kk][1]);
            uint32_t ph1 = pack_f16x2(s[2*kk][2],   s[2*kk][3]);
            uint32_t ph2 = pack_f16x2(s[2*kk+1][0], s[2*kk+1][1]);
            uint32_t ph3 = pack_f16x2(s[2*kk+1][2], s[2*kk+1][3]);
            #pragma unroll
            for (int jp = 0; jp < 4; ++jp) {
                const uint32_t off = laneV + kk * 2304 + jp * 32;
                uint32_t vh0, vh1, vh2, vh3;
                ldsm4t(vh0, vh1, vh2, vh3, VhB + off);
                mma_f16(acc[2*jp],   ph0, ph1, ph2, ph3, vh0, vh1);
                mma_f16(acc[2*jp+1], ph0, ph1, ph2, ph3, vh2, vh3);
            }
        }

        __syncthreads();                   // all warps done with buf[kt&1]
        stageTile(kt + 2, kt & 1);
    }

    // ================= peeled diagonal tile: kt = qt ========================
    {
        const int kt = qt;
        const int k0 = kt * BN;
        asm volatile("cp.async.wait_group 0;\n" ::: "memory");
        __syncthreads();

        const uint32_t sb  = smb + (kt & 1) * BUFB;
        const uint32_t KhB = sb, KlB = sb + ARRB, VhB = sb + 2 * ARRB;

        float s[8][4];
        #pragma unroll
        for (int j = 0; j < 8; ++j)
            #pragma unroll
            for (int i = 0; i < 4; ++i) s[j][i] = 0.f;

        // only jp <= w can touch at-or-below-diagonal columns
        for (int jp = 0; jp <= w; ++jp) {
            #pragma unroll
            for (int kk = 0; kk < 4; ++kk) {
                const uint32_t off = laneK + jp * 2304 + kk * 32;
                uint32_t kh0, kh1, kh2, kh3, kl0, kl1, kl2, kl3;
                ldsm4(kh0, kh1, kh2, kh3, KhB + off);
                ldsm4(kl0, kl1, kl2, kl3, KlB + off);
                mma_f16(s[2*jp],   qh[kk][0], qh[kk][1], qh[kk][2], qh[kk][3], kh0, kh1);
                mma_f16(s[2*jp],   ql[kk][0], ql[kk][1], ql[kk][2], ql[kk][3], kh0, kh1);
                mma_f16(s[2*jp],   qh[kk][0], qh[kk][1], qh[kk][2], qh[kk][3], kl0, kl1);
                mma_f16(s[2*jp+1], qh[kk][0], qh[kk][1], qh[kk][2], qh[kk][3], kh2, kh3);
                mma_f16(s[2*jp+1], ql[kk][0], ql[kk][1], ql[kk][2], ql[kk][3], kh2, kh3);
                mma_f16(s[2*jp+1], qh[kk][0], qh[kk][1], qh[kk][2], qh[kk][3], kl2, kl3);
            }
        }

        // mask: covers computed and skipped tiles alike (s was zero-init)
        #pragma unroll
        for (int j = 0; j < 8; ++j) {
            int n = k0 + j * 8 + 2 * c;
            if (n     > m_lo)     s[j][0] = -1e30f;
            if (n + 1 > m_lo)     s[j][1] = -1e30f;
            if (n     > m_lo + 8) s[j][2] = -1e30f;
            if (n + 1 > m_lo + 8) s[j][3] = -1e30f;
        }

        softmax_update(s);

        // P chunks kk > w are exactly zero -> skip
        for (int kk = 0; kk <= w; ++kk) {
            uint32_t ph0 = pack_f16x2(s[2*kk][0],   s[2*kk][1]);
            uint32_t ph1 = pack_f16x2(s[2*kk][2],   s[2*kk][3]);
            uint32_t ph2 = pack_f16x2(s[2*kk+1][0], s[2*kk+1][1]);
            uint32_t ph3 = pack_f16x2(s[2*kk+1][2], s[2*kk+1][3]);
            #pragma unroll
            for (int jp = 0; jp < 4; ++jp) {
                const uint32_t off = laneV + kk * 2304 + jp * 32;
                uint32_t vh0, vh1, vh2, vh3;
                ldsm4t(vh0, vh1, vh2, vh3, VhB + off);
                mma_f16(acc[2*jp],   ph0, ph1, ph2, ph3, vh0, vh1);
                mma_f16(acc[2*jp+1], ph0, ph1, ph2, ph3, vh2, vh3);
            }
        }
    }

    // ---- epilogue: reduce l across the quad, normalize, store ----
    l0 += __shfl_xor_sync(0xffffffffu, l0, 1);
    l0 += __shfl_xor_sync(0xffffffffu, l0, 2);
    l1 += __shfl_xor_sync(0xffffffffu, l1, 1);
    l1 += __shfl_xor_sync(0xffffffffu, l1, 2);
    const float inv0 = 1.f / l0, inv1 = 1.f / l1;
    #pragma unroll
    for (int jj = 0; jj < 8; ++jj) {
        float2 o0 = { acc[jj][0] * inv0, acc[jj][1] * inv0 };
        float2 o1 = { acc[jj][2] * inv1, acc[jj][3] * inv1 };
        *reinterpret_cast<float2*>(Op + (size_t)m_lo * RS + jj * 8 + 2 * c) = o0;
        *reinterpret_cast<float2*>(Op + (size_t)(m_lo + 8) * RS + jj * 8 + 2 * c) = o1;
    }
}

extern "C" void kernel_launch(void* const* d_in, const int* in_sizes, int n_in,
                              void* d_out, int out_size)
{
    const float* Q = (const float*)d_in[0];
    const float* K = (const float*)d_in[1];
    const float* V = (const float*)d_in[2];
    // d_in[3] = attn_mask (causal triu(k=1)) — applied analytically in-kernel.
    float* O = (float*)d_out;

    // 1) pre-pack K (hi/lo) and V (hi), tile-blocked
    int total = B_ * L_ * H_ * (ED / 4);
    prepack_kernel<<<(total + 255) / 256, 256>>>(K, V);

    // 2) attention
    cudaFuncSetAttribute(attn_kernel, cudaFuncAttributeMaxDynamicSharedMemorySize,
                         SMEM_BYTES);
    dim3 grid(L_ / BM, H_, B_);   // 32 x 16 x 2
    attn_kernel<<<grid, NT, SMEM_BYTES>>>(Q, O);
}